// round 1
// baseline (speedup 1.0000x reference)
#include <cuda_runtime.h>
#include <math.h>

#define DD   1024
#define NH   16
#define HDIM 64
#define FF   2048
#define BB   8
#define SS   1027
#define EPSL 1e-5f

__device__ float g_seq[(size_t)BB * SS * DD];
__device__ float g_scores[(size_t)BB * SS * NH];
__device__ float g_q0[DD];
__device__ float g_qhat[NH * DD];
__device__ float g_qb[NH];
__device__ float g_ctxp[(size_t)BB * 8 * NH * DD];
__device__ float g_oattn[BB * DD];
__device__ float g_ores[BB * DD];
__device__ float g_h1[BB * DD];
__device__ float g_f[BB * FF];
__device__ float g_f2[BB * DD];

__global__ void k_gemv(const float* __restrict__ W, const float* __restrict__ xin,
                       const float* __restrict__ bias, const float* __restrict__ residE,
                       const float* __restrict__ residB, float* __restrict__ out,
                       int IN, int OUT, int doRelu) {
    int b    = blockIdx.y;
    int e    = blockIdx.x * 8 + (threadIdx.x >> 5);
    int lane = threadIdx.x & 31;
    if (e >= OUT) return;
    const float4* Wr = (const float4*)(W + (size_t)e * IN);
    const float4* xr = (const float4*)(xin + (size_t)b * IN);
    int n4 = IN >> 2;
    float acc = 0.f;
    for (int i = lane; i < n4; i += 32) {
        float4 w = Wr[i], x = xr[i];
        acc += w.x * x.x + w.y * x.y + w.z * x.z + w.w * x.w;
    }
    #pragma unroll
    for (int o = 16; o; o >>= 1) acc += __shfl_xor_sync(0xffffffffu, acc, o);
    if (lane == 0) {
        float v = acc;
        if (bias)   v += bias[e];
        if (residE) v += residE[e];
        if (residB) v += residB[(size_t)b * OUT + e];
        if (doRelu) v = fmaxf(v, 0.f);
        out[(size_t)b * OUT + e] = v;
    }
}

__global__ void k_qhat(const float* __restrict__ Wqkv, const float* __restrict__ bqkv) {
    int h = blockIdx.x >> 2;
    int q = blockIdx.x & 3;
    int t = threadIdx.x;
    __shared__ float q0s[HDIM];
    if (t < HDIM) q0s[t] = g_q0[h * HDIM + t];
    __syncthreads();
    int d = q * 256 + t;
    float acc = 0.f;
    #pragma unroll 4
    for (int j = 0; j < HDIM; j++)
        acc += q0s[j] * Wqkv[(size_t)(DD + h * HDIM + j) * DD + d];
    g_qhat[h * DD + d] = acc;
    if (q == 0 && t == 0) {
        float s = 0.f;
        for (int j = 0; j < HDIM; j++) s += q0s[j] * bqkv[DD + h * HDIM + j];
        g_qb[h] = s;
    }
}

#define TS 16
__global__ void k_merge_scores(const float* __restrict__ x, const float* __restrict__ y,
                               const float* __restrict__ cls, const float* __restrict__ sep,
                               const float* __restrict__ px, const float* __restrict__ py,
                               const int* __restrict__ x_len, const int* __restrict__ y_len) {
    int b  = blockIdx.y;
    int s0 = blockIdx.x * TS;
    int lx = x_len[b], ly = y_len[b];
    int Sb = lx + ly + 3;
    int t  = threadIdx.x;
    int w  = t >> 5, lane = t & 31;

    float qreg[32];
    #pragma unroll
    for (int k = 0; k < 32; k++) qreg[k] = g_qhat[w * DD + lane + 32 * k];
    float qb = g_qb[w];

    __shared__ __align__(16) float sh[DD];

    int sEnd = min(s0 + TS, Sb);
    for (int s = s0; s < sEnd; s++) {
        float v0, v1;
        if (s == 0)            { v0 = cls[t]; v1 = cls[t + 512]; }
        else if (s <= lx)      { const float* xr = x + ((size_t)b * 512 + (s - 1)) * DD;
                                 v0 = xr[t] + px[t]; v1 = xr[t + 512] + px[t + 512]; }
        else if (s == lx + 1)  { v0 = sep[t]; v1 = sep[t + 512]; }
        else if (s <= lx + ly + 1) { const float* yr = y + ((size_t)b * 512 + (s - lx - 2)) * DD;
                                 v0 = yr[t] + py[t]; v1 = yr[t + 512] + py[t + 512]; }
        else                   { v0 = sep[t]; v1 = sep[t + 512]; }
        float* sq = g_seq + ((size_t)b * SS + s) * DD;
        sq[t] = v0; sq[t + 512] = v1;
        sh[t] = v0; sh[t + 512] = v1;
        __syncthreads();
        float acc = 0.f;
        #pragma unroll
        for (int k = 0; k < 32; k++) acc += sh[lane + 32 * k] * qreg[k];
        #pragma unroll
        for (int o = 16; o; o >>= 1) acc += __shfl_xor_sync(0xffffffffu, acc, o);
        if (lane == 0)
            g_scores[((size_t)b * SS + s) * NH + w] = (acc + qb) * 0.125f;
        __syncthreads();
    }
}

__global__ void k_softmax(const int* __restrict__ x_len, const int* __restrict__ y_len) {
    int b = blockIdx.x;
    int w = threadIdx.x >> 5, lane = threadIdx.x & 31;
    int Sb = x_len[b] + y_len[b] + 3;
    float* sc = g_scores + (size_t)b * SS * NH;
    float m = -1e30f;
    for (int s = lane; s < Sb; s += 32) m = fmaxf(m, sc[s * NH + w]);
    #pragma unroll
    for (int o = 16; o; o >>= 1) m = fmaxf(m, __shfl_xor_sync(0xffffffffu, m, o));
    float sum = 0.f;
    for (int s = lane; s < Sb; s += 32) {
        float e = __expf(sc[s * NH + w] - m);
        sc[s * NH + w] = e;
        sum += e;
    }
    #pragma unroll
    for (int o = 16; o; o >>= 1) sum += __shfl_xor_sync(0xffffffffu, sum, o);
    float inv = 1.f / sum;
    for (int s = lane; s < Sb; s += 32) sc[s * NH + w] *= inv;
}

__global__ void k_ctx(const int* __restrict__ x_len, const int* __restrict__ y_len) {
    int c = blockIdx.x;
    int dh = blockIdx.y;
    int b = blockIdx.z;
    int Sb = x_len[b] + y_len[b] + 3;
    int cl = (Sb + 7) >> 3;
    int s0 = c * cl, s1 = min(s0 + cl, Sb);
    int d = dh * 512 + threadIdx.x;

    float acc[NH];
    #pragma unroll
    for (int h = 0; h < NH; h++) acc[h] = 0.f;

    const float* seqb = g_seq + (size_t)b * SS * DD;
    const float4* at  = (const float4*)(g_scores + (size_t)b * SS * NH);
    for (int s = s0; s < s1; s++) {
        float sv = seqb[(size_t)s * DD + d];
        float4 a0 = at[s * 4 + 0], a1 = at[s * 4 + 1], a2 = at[s * 4 + 2], a3 = at[s * 4 + 3];
        acc[0]  += a0.x * sv; acc[1]  += a0.y * sv; acc[2]  += a0.z * sv; acc[3]  += a0.w * sv;
        acc[4]  += a1.x * sv; acc[5]  += a1.y * sv; acc[6]  += a1.z * sv; acc[7]  += a1.w * sv;
        acc[8]  += a2.x * sv; acc[9]  += a2.y * sv; acc[10] += a2.z * sv; acc[11] += a2.w * sv;
        acc[12] += a3.x * sv; acc[13] += a3.y * sv; acc[14] += a3.z * sv; acc[15] += a3.w * sv;
    }
    float* outp = g_ctxp + (((size_t)b * 8 + c) * NH) * DD + d;
    #pragma unroll
    for (int h = 0; h < NH; h++) outp[(size_t)h * DD] = acc[h];
}

__global__ void k_oattn(const float* __restrict__ Wqkv, const float* __restrict__ bqkv) {
    int h = blockIdx.x, b = blockIdx.y;
    int t = threadIdx.x;
    __shared__ __align__(16) float ctx[DD];
    for (int d = t; d < DD; d += 256) {
        float s = 0.f;
        #pragma unroll
        for (int c = 0; c < 8; c++)
            s += g_ctxp[(((size_t)b * 8 + c) * NH + h) * DD + d];
        ctx[d] = s;
    }
    __syncthreads();
    int w = t >> 5, lane = t & 31;
    const float4* ctx4 = (const float4*)ctx;
    for (int jj = 0; jj < 8; jj++) {
        int e = h * HDIM + w * 8 + jj;
        const float4* Wr = (const float4*)(Wqkv + (size_t)(2 * DD + e) * DD);
        float acc = 0.f;
        for (int i = lane; i < DD / 4; i += 32) {
            float4 wv = Wr[i]; float4 cv = ctx4[i];
            acc += wv.x * cv.x + wv.y * cv.y + wv.z * cv.z + wv.w * cv.w;
        }
        #pragma unroll
        for (int o = 16; o; o >>= 1) acc += __shfl_xor_sync(0xffffffffu, acc, o);
        if (lane == 0) g_oattn[(size_t)b * DD + e] = acc + bqkv[2 * DD + e];
    }
}

__global__ void k_ln(const float* __restrict__ in, const float* __restrict__ gamma,
                     const float* __restrict__ beta, float* __restrict__ out) {
    int b = blockIdx.x, t = threadIdx.x;
    const float* row = in + (size_t)b * DD;
    __shared__ float sred[8];
    __shared__ float smv[2];

    float s = 0.f;
    for (int i = t; i < DD; i += 256) s += row[i];
    #pragma unroll
    for (int o = 16; o; o >>= 1) s += __shfl_xor_sync(0xffffffffu, s, o);
    if ((t & 31) == 0) sred[t >> 5] = s;
    __syncthreads();
    if (t == 0) {
        float m = 0.f;
        #pragma unroll
        for (int i = 0; i < 8; i++) m += sred[i];
        smv[0] = m * (1.f / DD);
    }
    __syncthreads();
    float m = smv[0];

    float v = 0.f;
    for (int i = t; i < DD; i += 256) { float dd = row[i] - m; v += dd * dd; }
    #pragma unroll
    for (int o = 16; o; o >>= 1) v += __shfl_xor_sync(0xffffffffu, v, o);
    __syncthreads();
    if ((t & 31) == 0) sred[t >> 5] = v;
    __syncthreads();
    if (t == 0) {
        float vv = 0.f;
        #pragma unroll
        for (int i = 0; i < 8; i++) vv += sred[i];
        smv[1] = rsqrtf(vv * (1.f / DD) + EPSL);
    }
    __syncthreads();
    float r = smv[1];
    for (int i = t; i < DD; i += 256)
        out[(size_t)b * DD + i] = (row[i] - m) * r * gamma[i] + beta[i];
}

extern "C" void kernel_launch(void* const* d_in, const int* in_sizes, int n_in,
                              void* d_out, int out_size) {
    const float* x     = (const float*)d_in[0];
    const float* y     = (const float*)d_in[1];
    const float* cls   = (const float*)d_in[2];
    const float* sep   = (const float*)d_in[3];
    const float* px    = (const float*)d_in[4];
    const float* py    = (const float*)d_in[5];
    const float* Wqkv  = (const float*)d_in[6];
    const float* bqkv  = (const float*)d_in[7];
    const float* Wo    = (const float*)d_in[8];
    const float* bo    = (const float*)d_in[9];
    const float* W1    = (const float*)d_in[10];
    const float* b1    = (const float*)d_in[11];
    const float* W2    = (const float*)d_in[12];
    const float* b2    = (const float*)d_in[13];
    const float* ln1g  = (const float*)d_in[14];
    const float* ln1b  = (const float*)d_in[15];
    const float* ln2g  = (const float*)d_in[16];
    const float* ln2b  = (const float*)d_in[17];
    const int*   x_len = (const int*)d_in[18];
    const int*   y_len = (const int*)d_in[19];
    float* outp = (float*)d_out;

    float *p_q0, *p_oattn, *p_ores, *p_h1, *p_f, *p_f2;
    cudaGetSymbolAddress((void**)&p_q0,    g_q0);
    cudaGetSymbolAddress((void**)&p_oattn, g_oattn);
    cudaGetSymbolAddress((void**)&p_ores,  g_ores);
    cudaGetSymbolAddress((void**)&p_h1,    g_h1);
    cudaGetSymbolAddress((void**)&p_f,     g_f);
    cudaGetSymbolAddress((void**)&p_f2,    g_f2);

    k_gemv<<<dim3(128, 1), 256>>>(Wqkv, cls, bqkv, nullptr, nullptr, p_q0, DD, DD, 0);
    k_qhat<<<64, 256>>>(Wqkv, bqkv);
    k_merge_scores<<<dim3((SS + TS - 1) / TS, BB), 512>>>(x, y, cls, sep, px, py, x_len, y_len);
    k_softmax<<<BB, 512>>>(x_len, y_len);
    k_ctx<<<dim3(8, 2, BB), 512>>>(x_len, y_len);
    k_oattn<<<dim3(NH, BB), 256>>>(Wqkv, bqkv);
    k_gemv<<<dim3(128, BB), 256>>>(Wo, p_oattn, bo, cls, nullptr, p_ores, DD, DD, 0);
    k_ln<<<BB, 256>>>(p_ores, ln1g, ln1b, p_h1);
    k_gemv<<<dim3(256, BB), 256>>>(W1, p_h1, b1, nullptr, nullptr, p_f, DD, FF, 1);
    k_gemv<<<dim3(128, BB), 256>>>(W2, p_f, b2, nullptr, p_h1, p_f2, FF, DD, 0);
    k_ln<<<BB, 256>>>(p_f2, ln2g, ln2b, outp);
}